// round 3
// baseline (speedup 1.0000x reference)
#include <cuda_runtime.h>
#include <cuda_bf16.h>
#include <cstdint>

#define NQ 8192
#define NK 8192
#define KEEP 4096

// Offsets into the concatenated float32 output:
//   important_coords : [0,      16384)   (4096 x 4)
//   important_voxels : [16384,  98304)   (4096 x 5 x 4)
//   kept_importance  : [98304, 102400)   (4096 x 1)
//   importance       : [102400,110592)   (8192 x 1)
#define OFF_COORDS 0
#define OFF_VOX    16384
#define OFF_KIMP   98304
#define OFF_IMP    102400

// XLA EmitFastTanh (Eigen ptanh<float>) — exact coefficients, clamp, small-x path.
__device__ __forceinline__ float tanh_xla(float x) {
    float ax = fabsf(x);
    float xc = fminf(fmaxf(x, -7.90531110763549805f), 7.90531110763549805f);
    float x2 = xc * xc;
    float p = fmaf(x2, -2.76076847742355e-16f, 2.00018790482477e-13f);
    p = fmaf(x2, p, -8.60467152213735e-11f);
    p = fmaf(x2, p, 5.12229709037114e-08f);
    p = fmaf(x2, p, 1.48572235717979e-05f);
    p = fmaf(x2, p, 6.37261928875436e-04f);
    p = fmaf(x2, p, 4.89352455891786e-03f);
    p = xc * p;
    float q = fmaf(x2, 1.19825839466702e-06f, 1.18534705686654e-04f);
    q = fmaf(x2, q, 2.26843463243900e-03f);
    q = fmaf(x2, q, 4.89352518554385e-03f);
    float r = p / q;
    return (ax < 0.0004f) ? x : r;
}

// One warp per query: 3 passes over keys (max, sum-of-exp, attn-weighted coords),
// then lane 0 runs the 3->32->1 MLP + logistic and writes importance.
__global__ __launch_bounds__(256) void attn_kernel(
    const int4*   __restrict__ vc,     // voxel_coords (N,4) int32
    const float4* __restrict__ keys,   // important_conv_coords (M,4)
    const float*  __restrict__ w1,     // (3,32)
    const float*  __restrict__ b1,     // (32,)
    const float*  __restrict__ w2,     // (32,1)
    const float*  __restrict__ b2,     // (1,)
    float*        __restrict__ imp_out)
{
    int warp = (blockIdx.x * blockDim.x + threadIdx.x) >> 5;
    int lane = threadIdx.x & 31;
    if (warp >= NQ) return;

    int4 q = vc[warp];
    float qb = (float)q.x;
    float qz = (float)q.y, qy = (float)q.z, qx = (float)q.w;
    const float INV = 1.7320508075688772f;  // sqrt(3) as the divisor

    // pass 1: row max (masked entries are -1e9, matching reference)
    float mx = -3.0e38f;
    for (int m = lane; m < NK; m += 32) {
        float4 k = keys[m];
        float s = qz * k.y;
        s = fmaf(qy, k.z, s);
        s = fmaf(qx, k.w, s);
        s = s / INV;
        if (k.x != qb) s = -1.0e9f;
        mx = fmaxf(mx, s);
    }
    #pragma unroll
    for (int o = 16; o; o >>= 1) mx = fmaxf(mx, __shfl_xor_sync(0xffffffffu, mx, o));

    // pass 2: sum of exp(s - max). Terms with t < -80 are exactly absorbed (bit-safe skip).
    float sum = 0.0f;
    for (int m = lane; m < NK; m += 32) {
        float4 k = keys[m];
        float s = qz * k.y;
        s = fmaf(qy, k.z, s);
        s = fmaf(qx, k.w, s);
        s = s / INV;
        if (k.x != qb) s = -1.0e9f;
        float t = s - mx;
        if (t > -80.0f) sum += expf(t);
    }
    #pragma unroll
    for (int o = 16; o; o >>= 1) sum += __shfl_xor_sync(0xffffffffu, sum, o);

    // pass 3: coords_weight = sum_m (exp(t)/sum) * key  (per-element divide, as reference)
    float c0 = 0.0f, c1 = 0.0f, c2 = 0.0f;
    for (int m = lane; m < NK; m += 32) {
        float4 k = keys[m];
        float s = qz * k.y;
        s = fmaf(qy, k.z, s);
        s = fmaf(qx, k.w, s);
        s = s / INV;
        if (k.x != qb) s = -1.0e9f;
        float t = s - mx;
        if (t > -80.0f) {
            float a = expf(t) / sum;
            c0 = fmaf(a, k.y, c0);
            c1 = fmaf(a, k.z, c1);
            c2 = fmaf(a, k.w, c2);
        }
    }
    #pragma unroll
    for (int o = 16; o; o >>= 1) {
        c0 += __shfl_xor_sync(0xffffffffu, c0, o);
        c1 += __shfl_xor_sync(0xffffffffu, c1, o);
        c2 += __shfl_xor_sync(0xffffffffu, c2, o);
    }

    if (lane == 0) {
        float logit = 0.0f;
        #pragma unroll
        for (int j = 0; j < 32; j++) {
            float h = c0 * w1[j];
            h = fmaf(c1, w1[32 + j], h);
            h = fmaf(c2, w1[64 + j], h);
            h = h + b1[j];
            h = fmaxf(h, 0.0f);
            logit = fmaf(h, w2[j], logit);
        }
        logit = logit + b2[0];
        // XLA logistic: 0.5 + 0.5 * tanh(0.5 * x)
        float impv = 0.5f + 0.5f * tanh_xla(0.5f * logit);
        imp_out[warp] = impv;
    }
}

// One warp per voxel: stable-ascending rank via pairwise counting; kept rows scattered.
__global__ __launch_bounds__(256) void rank_kernel(
    const float* __restrict__ imp,     // importance (already in d_out tail)
    const int*   __restrict__ vc,      // voxel_coords (N,4)
    const float* __restrict__ voxels,  // (N,5,4) = 20 floats/row
    float*       __restrict__ out)
{
    int warp = (blockIdx.x * blockDim.x + threadIdx.x) >> 5;
    int lane = threadIdx.x & 31;
    if (warp >= NQ) return;

    float my = imp[warp];
    int cnt = 0;
    for (int j = lane; j < NQ; j += 32) {
        float v = imp[j];
        cnt += (int)(v < my) + (int)((v == my) && (j < warp));
    }
    #pragma unroll
    for (int o = 16; o; o >>= 1) cnt += __shfl_xor_sync(0xffffffffu, cnt, o);

    if (cnt >= KEEP) {
        int row = cnt - KEEP;
        if (lane < 20)
            out[OFF_VOX + row * 20 + lane] = voxels[warp * 20 + lane];
        if (lane < 4)
            out[OFF_COORDS + row * 4 + lane] = (float)vc[warp * 4 + lane];
        if (lane == 0)
            out[OFF_KIMP + row] = my;
    }
}

extern "C" void kernel_launch(void* const* d_in, const int* in_sizes, int n_in,
                              void* d_out, int out_size) {
    const int*   vc     = (const int*)d_in[0];
    const float* keys   = (const float*)d_in[1];
    const float* voxels = (const float*)d_in[2];
    const float* w1     = (const float*)d_in[3];
    const float* b1     = (const float*)d_in[4];
    const float* w2     = (const float*)d_in[5];
    const float* b2     = (const float*)d_in[6];
    float* out = (float*)d_out;
    float* imp = out + OFF_IMP;

    attn_kernel<<<1024, 256>>>((const int4*)vc, (const float4*)keys,
                               w1, b1, w2, b2, imp);
    rank_kernel<<<1024, 256>>>(imp, vc, voxels, out);
}

// round 5
// speedup vs baseline: 2.0248x; 2.0248x over previous
#include <cuda_runtime.h>
#include <cuda_bf16.h>
#include <cstdint>

#define NQ 8192
#define NK 8192
#define KEEP 4096

// Concatenated float32 output offsets
#define OFF_COORDS 0
#define OFF_VOX    16384
#define OFF_KIMP   98304
#define OFF_IMP    102400

#define SQRT3 1.7320508075688772f

// ---- persistent device scratch (allocation-free) ----
__device__ float4 g_keys[2][NK];        // keys grouped by batch, original order
__device__ int    g_kcnt[2];
__device__ int    g_qidx[2][NQ + 4];    // query indices grouped by batch (+pad)
__device__ int    g_qcnt[2];

// XLA EmitFastTanh (Eigen ptanh<float>) — exact coefficients, clamp, small-x path.
__device__ __forceinline__ float tanh_xla(float x) {
    float ax = fabsf(x);
    float xc = fminf(fmaxf(x, -7.90531110763549805f), 7.90531110763549805f);
    float x2 = xc * xc;
    float p = fmaf(x2, -2.76076847742355e-16f, 2.00018790482477e-13f);
    p = fmaf(x2, p, -8.60467152213735e-11f);
    p = fmaf(x2, p, 5.12229709037114e-08f);
    p = fmaf(x2, p, 1.48572235717979e-05f);
    p = fmaf(x2, p, 6.37261928875436e-04f);
    p = fmaf(x2, p, 4.89352455891786e-03f);
    p = xc * p;
    float q = fmaf(x2, 1.19825839466702e-06f, 1.18534705686654e-04f);
    q = fmaf(x2, q, 2.26843463243900e-03f);
    q = fmaf(x2, q, 4.89352518554385e-03f);
    float r = p / q;
    return (ax < 0.0004f) ? x : r;
}

// Deterministic stable compaction by batch. block 0: keys, block 1: queries.
__global__ __launch_bounds__(1024) void partition_kernel(
    const int4* __restrict__ vc, const float4* __restrict__ keys)
{
    __shared__ int sc[1024];
    int t = threadIdx.x;

    if (blockIdx.x == 0) {
        float4 kv[8];
        int cnt = 0;
        #pragma unroll
        for (int e = 0; e < 8; e++) {
            kv[e] = keys[8 * t + e];
            cnt += (kv[e].x == 0.0f) ? 1 : 0;
        }
        sc[t] = cnt; __syncthreads();
        for (int off = 1; off < 1024; off <<= 1) {
            int a = (t >= off) ? sc[t - off] : 0;
            __syncthreads();
            sc[t] += a;
            __syncthreads();
        }
        int tot0 = sc[1023];
        int p0 = sc[t] - cnt;
        int p1 = 8 * t - p0;
        #pragma unroll
        for (int e = 0; e < 8; e++) {
            if (kv[e].x == 0.0f) g_keys[0][p0++] = kv[e];
            else                 g_keys[1][p1++] = kv[e];
        }
        if (t == 0) { g_kcnt[0] = tot0; g_kcnt[1] = NK - tot0; }
    } else {
        int qb[8];
        int cnt = 0;
        #pragma unroll
        for (int e = 0; e < 8; e++) {
            qb[e] = vc[8 * t + e].x;
            cnt += (qb[e] == 0) ? 1 : 0;
        }
        sc[t] = cnt; __syncthreads();
        for (int off = 1; off < 1024; off <<= 1) {
            int a = (t >= off) ? sc[t - off] : 0;
            __syncthreads();
            sc[t] += a;
            __syncthreads();
        }
        int tot0 = sc[1023];
        int p0 = sc[t] - cnt;
        int p1 = 8 * t - p0;
        #pragma unroll
        for (int e = 0; e < 8; e++) {
            int idx = 8 * t + e;
            if (qb[e] == 0) g_qidx[0][p0++] = idx;
            else            g_qidx[1][p1++] = idx;
        }
        __syncthreads();
        if (t == 0) {
            g_qcnt[0] = tot0; g_qcnt[1] = NQ - tot0;
            #pragma unroll
            for (int b = 0; b < 2; b++) {
                int c = (b == 0) ? tot0 : (NQ - tot0);
                if (c > 0) {
                    int last = g_qidx[b][c - 1];
                    int cpad = (c + 3) & ~3;
                    for (int i = c; i < cpad; i++) g_qidx[b][i] = last;
                }
            }
        }
    }
}

// One warp handles 4 same-batch queries. 3 passes over the batch's compact keys.
// Pass 1 in dot-space (division is monotone => max commutes, single / per query).
// Passes 2/3 prefilter in dot-space; exact reference math on survivors.
__global__ __launch_bounds__(256) void attn_kernel(
    const int4*  __restrict__ vc,
    const float* __restrict__ w1,
    const float* __restrict__ b1,
    const float* __restrict__ w2,
    const float* __restrict__ b2,
    float*       __restrict__ imp_out)
{
    int warp = (blockIdx.x * blockDim.x + threadIdx.x) >> 5;
    int lane = threadIdx.x & 31;

    int ngrp0 = (g_qcnt[0] + 3) >> 2;
    int ngrp1 = (g_qcnt[1] + 3) >> 2;
    int b, g;
    if (warp < ngrp0)              { b = 0; g = warp; }
    else if (warp < ngrp0 + ngrp1) { b = 1; g = warp - ngrp0; }
    else return;

    int qi[4];
    float qz[4], qy[4], qx[4];
    #pragma unroll
    for (int i = 0; i < 4; i++) {
        qi[i] = g_qidx[b][4 * g + i];
        int4 q = vc[qi[i]];
        qz[i] = (float)q.y; qy[i] = (float)q.z; qx[i] = (float)q.w;
    }

    const float4* kl = g_keys[b];
    int kc = g_kcnt[b];

    // ---- pass 1: max in dot-space ----
    float mxd[4] = {-3.0e38f, -3.0e38f, -3.0e38f, -3.0e38f};
    for (int m = lane; m < kc; m += 32) {
        float4 k = kl[m];
        #pragma unroll
        for (int i = 0; i < 4; i++) {
            float d = qz[i] * k.y;
            d = fmaf(qy[i], k.z, d);
            d = fmaf(qx[i], k.w, d);
            mxd[i] = fmaxf(mxd[i], d);
        }
    }
    #pragma unroll
    for (int o = 16; o; o >>= 1)
        #pragma unroll
        for (int i = 0; i < 4; i++)
            mxd[i] = fmaxf(mxd[i], __shfl_xor_sync(0xffffffffu, mxd[i], o));

    float mx[4], thr[4];
    #pragma unroll
    for (int i = 0; i < 4; i++) {
        mx[i]  = mxd[i] / SQRT3;                  // == max(dot/sqrt3), monotone
        thr[i] = (mx[i] - 88.0f) * SQRT3;         // conservative dot-space prefilter
    }

    // ---- pass 2: sum of exp(s - mx) ----
    float sum[4] = {0.0f, 0.0f, 0.0f, 0.0f};
    for (int m = lane; m < kc; m += 32) {
        float4 k = kl[m];
        #pragma unroll
        for (int i = 0; i < 4; i++) {
            float d = qz[i] * k.y;
            d = fmaf(qy[i], k.z, d);
            d = fmaf(qx[i], k.w, d);
            if (d > thr[i]) {
                float s = d / SQRT3;
                float t = s - mx[i];
                if (t > -80.0f) sum[i] += expf(t);
            }
        }
    }
    #pragma unroll
    for (int o = 16; o; o >>= 1)
        #pragma unroll
        for (int i = 0; i < 4; i++)
            sum[i] += __shfl_xor_sync(0xffffffffu, sum[i], o);

    // ---- pass 3: attn-weighted coords (per-element exp/sum, as reference) ----
    float c0[4] = {0,0,0,0}, c1[4] = {0,0,0,0}, c2[4] = {0,0,0,0};
    for (int m = lane; m < kc; m += 32) {
        float4 k = kl[m];
        #pragma unroll
        for (int i = 0; i < 4; i++) {
            float d = qz[i] * k.y;
            d = fmaf(qy[i], k.z, d);
            d = fmaf(qx[i], k.w, d);
            if (d > thr[i]) {
                float s = d / SQRT3;
                float t = s - mx[i];
                if (t > -80.0f) {
                    float a = expf(t) / sum[i];
                    c0[i] = fmaf(a, k.y, c0[i]);
                    c1[i] = fmaf(a, k.z, c1[i]);
                    c2[i] = fmaf(a, k.w, c2[i]);
                }
            }
        }
    }
    #pragma unroll
    for (int o = 16; o; o >>= 1)
        #pragma unroll
        for (int i = 0; i < 4; i++) {
            c0[i] += __shfl_xor_sync(0xffffffffu, c0[i], o);
            c1[i] += __shfl_xor_sync(0xffffffffu, c1[i], o);
            c2[i] += __shfl_xor_sync(0xffffffffu, c2[i], o);
        }

    // ---- MLP + logistic: lane i handles query i (statically unrolled) ----
    #pragma unroll
    for (int i = 0; i < 4; i++) {
        if (lane == i) {
            float C0 = c0[i], C1 = c1[i], C2 = c2[i];
            float logit = 0.0f;
            #pragma unroll
            for (int j = 0; j < 32; j++) {
                float h = C0 * w1[j];
                h = fmaf(C1, w1[32 + j], h);
                h = fmaf(C2, w1[64 + j], h);
                h = h + b1[j];
                h = fmaxf(h, 0.0f);
                logit = fmaf(h, w2[j], logit);
            }
            logit = logit + b2[0];
            imp_out[qi[i]] = 0.5f + 0.5f * tanh_xla(0.5f * logit);
        }
    }
}

// One warp per 4 voxels: stable-ascending rank by pairwise counting (float4 loads).
__global__ __launch_bounds__(256) void rank_kernel(
    const float* __restrict__ imp,
    const int*   __restrict__ vc,
    const float* __restrict__ voxels,
    float*       __restrict__ out)
{
    int warp = (blockIdx.x * blockDim.x + threadIdx.x) >> 5;
    int lane = threadIdx.x & 31;
    if (warp >= NQ / 4) return;

    int base = 4 * warp;
    float my[4];
    #pragma unroll
    for (int i = 0; i < 4; i++) my[i] = imp[base + i];

    int cnt[4] = {0, 0, 0, 0};
    const float4* imp4 = (const float4*)imp;
    for (int j4 = lane; j4 < NQ / 4; j4 += 32) {
        float4 v = imp4[j4];
        int j = 4 * j4;
        #pragma unroll
        for (int i = 0; i < 4; i++) {
            int q = base + i;
            cnt[i] += (int)(v.x < my[i]) + (int)((v.x == my[i]) && (j + 0 < q));
            cnt[i] += (int)(v.y < my[i]) + (int)((v.y == my[i]) && (j + 1 < q));
            cnt[i] += (int)(v.z < my[i]) + (int)((v.z == my[i]) && (j + 2 < q));
            cnt[i] += (int)(v.w < my[i]) + (int)((v.w == my[i]) && (j + 3 < q));
        }
    }
    #pragma unroll
    for (int o = 16; o; o >>= 1)
        #pragma unroll
        for (int i = 0; i < 4; i++)
            cnt[i] += __shfl_xor_sync(0xffffffffu, cnt[i], o);

    #pragma unroll
    for (int i = 0; i < 4; i++) {
        if (cnt[i] >= KEEP) {
            int q = base + i;
            int row = cnt[i] - KEEP;
            if (lane < 20)
                out[OFF_VOX + row * 20 + lane] = voxels[q * 20 + lane];
            if (lane < 4)
                out[OFF_COORDS + row * 4 + lane] = (float)vc[q * 4 + lane];
            if (lane == 0)
                out[OFF_KIMP + row] = my[i];
        }
    }
}

extern "C" void kernel_launch(void* const* d_in, const int* in_sizes, int n_in,
                              void* d_out, int out_size) {
    const int*   vc     = (const int*)d_in[0];
    const float* keys   = (const float*)d_in[1];
    const float* voxels = (const float*)d_in[2];
    const float* w1     = (const float*)d_in[3];
    const float* b1     = (const float*)d_in[4];
    const float* w2     = (const float*)d_in[5];
    const float* b2     = (const float*)d_in[6];
    float* out = (float*)d_out;
    float* imp = out + OFF_IMP;

    partition_kernel<<<2, 1024>>>((const int4*)vc, (const float4*)keys);
    attn_kernel<<<258, 256>>>((const int4*)vc, w1, b1, w2, b2, imp);
    rank_kernel<<<256, 256>>>(imp, vc, voxels, out);
}

// round 8
// speedup vs baseline: 2.6418x; 1.3047x over previous
#include <cuda_runtime.h>
#include <cuda_bf16.h>
#include <cstdint>

#define NQ 8192
#define NK 8192
#define KEEP 4096

// Concatenated float32 output offsets
#define OFF_COORDS 0
#define OFF_VOX    16384
#define OFF_KIMP   98304
#define OFF_IMP    102400

#define SQRT3 1.7320508075688772f

// ---- persistent device scratch (allocation-free) ----
__device__ float4 g_keys[2][NK];     // keys grouped by batch, stable original order
__device__ int    g_kcnt[2];
__device__ int    g_qidx[2][NQ];     // query indices grouped by batch, stable
__device__ int    g_qcnt[2];
__device__ int    g_bc[64];          // per-block batch-0 counts: [0,32)=keys [32,64)=queries

// XLA EmitFastTanh (Eigen ptanh<float>) — exact coefficients, clamp, small-x path.
__device__ __forceinline__ float tanh_xla(float x) {
    float ax = fabsf(x);
    float xc = fminf(fmaxf(x, -7.90531110763549805f), 7.90531110763549805f);
    float x2 = xc * xc;
    float p = fmaf(x2, -2.76076847742355e-16f, 2.00018790482477e-13f);
    p = fmaf(x2, p, -8.60467152213735e-11f);
    p = fmaf(x2, p, 5.12229709037114e-08f);
    p = fmaf(x2, p, 1.48572235717979e-05f);
    p = fmaf(x2, p, 6.37261928875436e-04f);
    p = fmaf(x2, p, 4.89352455891786e-03f);
    p = xc * p;
    float q = fmaf(x2, 1.19825839466702e-06f, 1.18534705686654e-04f);
    q = fmaf(x2, q, 2.26843463243900e-03f);
    q = fmaf(x2, q, 4.89352518554385e-03f);
    float r = p / q;
    return (ax < 0.0004f) ? x : r;
}

// ---- partition phase 1: per-block batch-0 counts (64 blocks x 256 threads) ----
__global__ __launch_bounds__(256) void count_kernel(
    const int4* __restrict__ vc, const float4* __restrict__ keys)
{
    __shared__ int ws[8];
    int b = blockIdx.x, t = threadIdx.x;
    int flag;
    if (b < 32) flag = (keys[b * 256 + t].x == 0.0f) ? 1 : 0;
    else        flag = (vc[(b - 32) * 256 + t].x == 0) ? 1 : 0;
    unsigned bal = __ballot_sync(0xffffffffu, flag);
    if ((t & 31) == 0) ws[t >> 5] = __popc(bal);
    __syncthreads();
    if (t == 0) {
        int s = 0;
        #pragma unroll
        for (int i = 0; i < 8; i++) s += ws[i];
        g_bc[b] = s;
    }
}

// ---- partition phase 2: stable scatter (64 blocks x 256 threads) ----
__global__ __launch_bounds__(256) void scatter_kernel(
    const int4* __restrict__ vc, const float4* __restrict__ keys)
{
    __shared__ int ws[8];
    __shared__ int s_pre0, s_tot0;
    int b = blockIdx.x, t = threadIdx.x;
    bool isKey = (b < 32);
    int c = isKey ? b : b - 32;
    int grp = isKey ? 0 : 32;

    if (t < 32) {
        int v = g_bc[grp + t];
        int x = v;
        #pragma unroll
        for (int o = 1; o < 32; o <<= 1) {
            int y = __shfl_up_sync(0xffffffffu, x, o);
            if (t >= o) x += y;
        }
        if (t == c)  s_pre0 = x - v;   // batch-0 elems in earlier blocks
        if (t == 31) s_tot0 = x;       // total batch-0 in this group
    }
    __syncthreads();

    int i = c * 256 + t;
    int flag;
    float4 kv; int4 qv;
    if (isKey) { kv = keys[i]; flag = (kv.x == 0.0f) ? 1 : 0; }
    else       { qv = vc[i];   flag = (qv.x == 0) ? 1 : 0; }

    unsigned bal = __ballot_sync(0xffffffffu, flag);
    int lane = t & 31, w = t >> 5;
    int lpre = __popc(bal & ((1u << lane) - 1u));
    if (lane == 0) ws[w] = __popc(bal);
    __syncthreads();
    int wpre = 0;
    for (int j = 0; j < w; j++) wpre += ws[j];

    int pos0 = s_pre0 + wpre + lpre;
    int pos1 = i - pos0;
    if (isKey) {
        if (flag) g_keys[0][pos0] = kv; else g_keys[1][pos1] = kv;
        if (t == 0 && c == 0) { g_kcnt[0] = s_tot0; g_kcnt[1] = NK - s_tot0; }
    } else {
        if (flag) g_qidx[0][pos0] = i; else g_qidx[1][pos1] = i;
        if (t == 0 && c == 0) { g_qcnt[0] = s_tot0; g_qcnt[1] = NQ - s_tot0; }
    }
}

// ---- attention: 4 same-batch queries per warp, 2 key sweeps, 4x unrolled ----
#define DOT(k, i) (fmaf(qx[i], (k).w, fmaf(qy[i], (k).z, qz[i] * (k).y)))

#define P1BODY(k)                                        \
    {   _Pragma("unroll")                                 \
        for (int i = 0; i < 4; i++)                       \
            mxd[i] = fmaxf(mxd[i], DOT(k, i)); }

#define P2BODY(k)                                        \
    {   _Pragma("unroll")                                 \
        for (int i = 0; i < 4; i++) {                     \
            float d = DOT(k, i);                          \
            if (d > thr[i]) {                             \
                float s = d / SQRT3;                      \
                float t2 = s - mx[i];                     \
                if (t2 > -80.0f) {                        \
                    float a = expf(t2);                   \
                    sum[i] += a;                          \
                    c0[i] = fmaf(a, (k).y, c0[i]);        \
                    c1[i] = fmaf(a, (k).z, c1[i]);        \
                    c2[i] = fmaf(a, (k).w, c2[i]);        \
                } } } }

__global__ __launch_bounds__(256) void attn_kernel(
    const int4*  __restrict__ vc,
    const float* __restrict__ w1,
    const float* __restrict__ b1,
    const float* __restrict__ w2,
    const float* __restrict__ b2,
    float*       __restrict__ imp_out)
{
    int warp = (blockIdx.x * blockDim.x + threadIdx.x) >> 5;
    int lane = threadIdx.x & 31;

    int qc0 = g_qcnt[0], qc1 = g_qcnt[1];
    int ngrp0 = (qc0 + 3) >> 2;
    int ngrp1 = (qc1 + 3) >> 2;
    int b, g, qc;
    if (warp < ngrp0)              { b = 0; g = warp;         qc = qc0; }
    else if (warp < ngrp0 + ngrp1) { b = 1; g = warp - ngrp0; qc = qc1; }
    else return;
    if (qc == 0) return;

    int qi[4];
    float qz[4], qy[4], qx[4];
    #pragma unroll
    for (int i = 0; i < 4; i++) {
        int idx = 4 * g + i;
        qi[i] = g_qidx[b][idx < qc ? idx : qc - 1];
        int4 q = vc[qi[i]];
        qz[i] = (float)q.y; qy[i] = (float)q.z; qx[i] = (float)q.w;
    }

    const float4* kl = g_keys[b];
    int kc = g_kcnt[b];

    // ---- pass 1: max in dot-space (monotone => single divide later) ----
    float mxd[4] = {-3.0e38f, -3.0e38f, -3.0e38f, -3.0e38f};
    {
        int m = lane;
        for (; m + 96 < kc; m += 128) {
            float4 ka = kl[m], kb = kl[m + 32], kd = kl[m + 64], ke = kl[m + 96];
            P1BODY(ka) P1BODY(kb) P1BODY(kd) P1BODY(ke)
        }
        for (; m < kc; m += 32) { float4 ka = kl[m]; P1BODY(ka) }
    }
    #pragma unroll
    for (int o = 16; o; o >>= 1)
        #pragma unroll
        for (int i = 0; i < 4; i++)
            mxd[i] = fmaxf(mxd[i], __shfl_xor_sync(0xffffffffu, mxd[i], o));

    float mx[4], thr[4];
    #pragma unroll
    for (int i = 0; i < 4; i++) {
        mx[i]  = mxd[i] / SQRT3;
        thr[i] = (mx[i] - 88.0f) * SQRT3;   // conservative dot-space prefilter
    }

    // ---- pass 2 (fused): sum of exp AND unnormalized weighted coords ----
    float sum[4] = {0, 0, 0, 0};
    float c0[4] = {0, 0, 0, 0}, c1[4] = {0, 0, 0, 0}, c2[4] = {0, 0, 0, 0};
    {
        int m = lane;
        for (; m + 96 < kc; m += 128) {
            float4 ka = kl[m], kb = kl[m + 32], kd = kl[m + 64], ke = kl[m + 96];
            P2BODY(ka) P2BODY(kb) P2BODY(kd) P2BODY(ke)
        }
        for (; m < kc; m += 32) { float4 ka = kl[m]; P2BODY(ka) }
    }
    #pragma unroll
    for (int o = 16; o; o >>= 1)
        #pragma unroll
        for (int i = 0; i < 4; i++) {
            sum[i] += __shfl_xor_sync(0xffffffffu, sum[i], o);
            c0[i]  += __shfl_xor_sync(0xffffffffu, c0[i], o);
            c1[i]  += __shfl_xor_sync(0xffffffffu, c1[i], o);
            c2[i]  += __shfl_xor_sync(0xffffffffu, c2[i], o);
        }

    // ---- MLP + logistic: lane i handles query i ----
    #pragma unroll
    for (int i = 0; i < 4; i++) {
        if (lane == i) {
            float C0 = c0[i] / sum[i];
            float C1 = c1[i] / sum[i];
            float C2 = c2[i] / sum[i];
            float logit = 0.0f;
            #pragma unroll
            for (int j = 0; j < 32; j++) {
                float h = C0 * w1[j];
                h = fmaf(C1, w1[32 + j], h);
                h = fmaf(C2, w1[64 + j], h);
                h = h + b1[j];
                h = fmaxf(h, 0.0f);
                logit = fmaf(h, w2[j], logit);
            }
            logit = logit + b2[0];
            imp_out[qi[i]] = 0.5f + 0.5f * tanh_xla(0.5f * logit);
        }
    }
}

// ---- stable-ascending rank via pairwise counting; 4 voxels per warp ----
__global__ __launch_bounds__(256) void rank_kernel(
    const float* __restrict__ imp,
    const int*   __restrict__ vc,
    const float* __restrict__ voxels,
    float*       __restrict__ out)
{
    int warp = (blockIdx.x * blockDim.x + threadIdx.x) >> 5;
    int lane = threadIdx.x & 31;
    if (warp >= NQ / 4) return;

    int base = 4 * warp;
    float my[4];
    #pragma unroll
    for (int i = 0; i < 4; i++) my[i] = imp[base + i];

    int cnt[4] = {0, 0, 0, 0};
    const float4* imp4 = (const float4*)imp;
    for (int j4 = lane; j4 < NQ / 4; j4 += 32) {
        float4 v = imp4[j4];
        int j = 4 * j4;
        #pragma unroll
        for (int i = 0; i < 4; i++) {
            int q = base + i;
            cnt[i] += (int)(v.x < my[i]) + (int)((v.x == my[i]) && (j + 0 < q));
            cnt[i] += (int)(v.y < my[i]) + (int)((v.y == my[i]) && (j + 1 < q));
            cnt[i] += (int)(v.z < my[i]) + (int)((v.z == my[i]) && (j + 2 < q));
            cnt[i] += (int)(v.w < my[i]) + (int)((v.w == my[i]) && (j + 3 < q));
        }
    }
    #pragma unroll
    for (int o = 16; o; o >>= 1)
        #pragma unroll
        for (int i = 0; i < 4; i++)
            cnt[i] += __shfl_xor_sync(0xffffffffu, cnt[i], o);

    #pragma unroll
    for (int i = 0; i < 4; i++) {
        if (cnt[i] >= KEEP) {
            int q = base + i;
            int row = cnt[i] - KEEP;
            if (lane < 20)
                out[OFF_VOX + row * 20 + lane] = voxels[q * 20 + lane];
            if (lane < 4)
                out[OFF_COORDS + row * 4 + lane] = (float)vc[q * 4 + lane];
            if (lane == 0)
                out[OFF_KIMP + row] = my[i];
        }
    }
}

extern "C" void kernel_launch(void* const* d_in, const int* in_sizes, int n_in,
                              void* d_out, int out_size) {
    const int*   vc     = (const int*)d_in[0];
    const float* keys   = (const float*)d_in[1];
    const float* voxels = (const float*)d_in[2];
    const float* w1     = (const float*)d_in[3];
    const float* b1     = (const float*)d_in[4];
    const float* w2     = (const float*)d_in[5];
    const float* b2     = (const float*)d_in[6];
    float* out = (float*)d_out;
    float* imp = out + OFF_IMP;

    count_kernel<<<64, 256>>>((const int4*)vc, (const float4*)keys);
    scatter_kernel<<<64, 256>>>((const int4*)vc, (const float4*)keys);
    attn_kernel<<<258, 256>>>((const int4*)vc, w1, b1, w2, b2, imp);
    rank_kernel<<<256, 256>>>(imp, vc, voxels, out);
}

// round 9
// speedup vs baseline: 2.7621x; 1.0455x over previous
#include <cuda_runtime.h>
#include <cuda_bf16.h>
#include <cstdint>

#define NQ 8192
#define NK 8192
#define KEEP 4096

// Concatenated float32 output offsets
#define OFF_COORDS 0
#define OFF_VOX    16384
#define OFF_KIMP   98304
#define OFF_IMP    102400

#define SQRT3 1.7320508075688772f

// ---- persistent device scratch (allocation-free) ----
__device__ float4 g_keys[2][NK];     // keys grouped by batch, stable original order
__device__ int    g_kcnt[2];
__device__ int    g_qidx[2][NQ];     // query indices grouped by batch, stable
__device__ int    g_qcnt[2];
__device__ int    g_bc[64];          // per-block batch-0 counts: [0,32)=keys [32,64)=queries

// XLA EmitFastTanh (Eigen ptanh<float>) — exact coefficients, clamp, small-x path.
__device__ __forceinline__ float tanh_xla(float x) {
    float ax = fabsf(x);
    float xc = fminf(fmaxf(x, -7.90531110763549805f), 7.90531110763549805f);
    float x2 = xc * xc;
    float p = fmaf(x2, -2.76076847742355e-16f, 2.00018790482477e-13f);
    p = fmaf(x2, p, -8.60467152213735e-11f);
    p = fmaf(x2, p, 5.12229709037114e-08f);
    p = fmaf(x2, p, 1.48572235717979e-05f);
    p = fmaf(x2, p, 6.37261928875436e-04f);
    p = fmaf(x2, p, 4.89352455891786e-03f);
    p = xc * p;
    float q = fmaf(x2, 1.19825839466702e-06f, 1.18534705686654e-04f);
    q = fmaf(x2, q, 2.26843463243900e-03f);
    q = fmaf(x2, q, 4.89352518554385e-03f);
    float r = p / q;
    return (ax < 0.0004f) ? x : r;
}

// ---- partition phase 1: per-block batch-0 counts (64 blocks x 256 threads) ----
__global__ __launch_bounds__(256) void count_kernel(
    const int4* __restrict__ vc, const float4* __restrict__ keys)
{
    __shared__ int ws[8];
    int b = blockIdx.x, t = threadIdx.x;
    int flag;
    if (b < 32) flag = (keys[b * 256 + t].x == 0.0f) ? 1 : 0;
    else        flag = (vc[(b - 32) * 256 + t].x == 0) ? 1 : 0;
    unsigned bal = __ballot_sync(0xffffffffu, flag);
    if ((t & 31) == 0) ws[t >> 5] = __popc(bal);
    __syncthreads();
    if (t == 0) {
        int s = 0;
        #pragma unroll
        for (int i = 0; i < 8; i++) s += ws[i];
        g_bc[b] = s;
    }
}

// ---- partition phase 2: stable scatter (64 blocks x 256 threads) ----
__global__ __launch_bounds__(256) void scatter_kernel(
    const int4* __restrict__ vc, const float4* __restrict__ keys)
{
    __shared__ int ws[8];
    __shared__ int s_pre0, s_tot0;
    int b = blockIdx.x, t = threadIdx.x;
    bool isKey = (b < 32);
    int c = isKey ? b : b - 32;
    int grp = isKey ? 0 : 32;

    if (t < 32) {
        int v = g_bc[grp + t];
        int x = v;
        #pragma unroll
        for (int o = 1; o < 32; o <<= 1) {
            int y = __shfl_up_sync(0xffffffffu, x, o);
            if (t >= o) x += y;
        }
        if (t == c)  s_pre0 = x - v;   // batch-0 elems in earlier blocks
        if (t == 31) s_tot0 = x;       // total batch-0 in this group
    }
    __syncthreads();

    int i = c * 256 + t;
    int flag;
    float4 kv; int4 qv;
    if (isKey) { kv = keys[i]; flag = (kv.x == 0.0f) ? 1 : 0; }
    else       { qv = vc[i];   flag = (qv.x == 0) ? 1 : 0; }

    unsigned bal = __ballot_sync(0xffffffffu, flag);
    int lane = t & 31, w = t >> 5;
    int lpre = __popc(bal & ((1u << lane) - 1u));
    if (lane == 0) ws[w] = __popc(bal);
    __syncthreads();
    int wpre = 0;
    for (int j = 0; j < w; j++) wpre += ws[j];

    int pos0 = s_pre0 + wpre + lpre;
    int pos1 = i - pos0;
    if (isKey) {
        if (flag) g_keys[0][pos0] = kv; else g_keys[1][pos1] = kv;
        if (t == 0 && c == 0) { g_kcnt[0] = s_tot0; g_kcnt[1] = NK - s_tot0; }
    } else {
        if (flag) g_qidx[0][pos0] = i; else g_qidx[1][pos1] = i;
        if (t == 0 && c == 0) { g_qcnt[0] = s_tot0; g_qcnt[1] = NQ - s_tot0; }
    }
}

// ---- attention: 2 same-batch queries per warp, 2 key sweeps, 4x unrolled ----
#define QPW 2
#define DOT(k, i) (fmaf(qx[i], (k).w, fmaf(qy[i], (k).z, qz[i] * (k).y)))

#define P1BODY(k)                                        \
    {   _Pragma("unroll")                                 \
        for (int i = 0; i < QPW; i++)                     \
            mxd[i] = fmaxf(mxd[i], DOT(k, i)); }

#define P2BODY(k)                                        \
    {   _Pragma("unroll")                                 \
        for (int i = 0; i < QPW; i++) {                   \
            float d = DOT(k, i);                          \
            if (d > thr[i]) {                             \
                float s = d / SQRT3;                      \
                float t2 = s - mx[i];                     \
                if (t2 > -80.0f) {                        \
                    float a = expf(t2);                   \
                    sum[i] += a;                          \
                    c0[i] = fmaf(a, (k).y, c0[i]);        \
                    c1[i] = fmaf(a, (k).z, c1[i]);        \
                    c2[i] = fmaf(a, (k).w, c2[i]);        \
                } } } }

__global__ __launch_bounds__(256) void attn_kernel(
    const int4*  __restrict__ vc,
    const float* __restrict__ w1,
    const float* __restrict__ b1,
    const float* __restrict__ w2,
    const float* __restrict__ b2,
    float*       __restrict__ imp_out)
{
    int warp = (blockIdx.x * blockDim.x + threadIdx.x) >> 5;
    int lane = threadIdx.x & 31;

    int qc0 = g_qcnt[0], qc1 = g_qcnt[1];
    int ngrp0 = (qc0 + QPW - 1) / QPW;
    int ngrp1 = (qc1 + QPW - 1) / QPW;
    int b, g, qc;
    if (warp < ngrp0)              { b = 0; g = warp;         qc = qc0; }
    else if (warp < ngrp0 + ngrp1) { b = 1; g = warp - ngrp0; qc = qc1; }
    else return;
    if (qc == 0) return;

    int qi[QPW];
    float qz[QPW], qy[QPW], qx[QPW];
    #pragma unroll
    for (int i = 0; i < QPW; i++) {
        int idx = QPW * g + i;
        qi[i] = g_qidx[b][idx < qc ? idx : qc - 1];
        int4 q = vc[qi[i]];
        qz[i] = (float)q.y; qy[i] = (float)q.z; qx[i] = (float)q.w;
    }

    const float4* kl = g_keys[b];
    int kc = g_kcnt[b];

    // ---- pass 1: max in dot-space (monotone => single divide later) ----
    float mxd[QPW];
    #pragma unroll
    for (int i = 0; i < QPW; i++) mxd[i] = -3.0e38f;
    {
        int m = lane;
        for (; m + 96 < kc; m += 128) {
            float4 ka = kl[m], kb = kl[m + 32], kd = kl[m + 64], ke = kl[m + 96];
            P1BODY(ka) P1BODY(kb) P1BODY(kd) P1BODY(ke)
        }
        for (; m < kc; m += 32) { float4 ka = kl[m]; P1BODY(ka) }
    }
    #pragma unroll
    for (int o = 16; o; o >>= 1)
        #pragma unroll
        for (int i = 0; i < QPW; i++)
            mxd[i] = fmaxf(mxd[i], __shfl_xor_sync(0xffffffffu, mxd[i], o));

    float mx[QPW], thr[QPW];
    #pragma unroll
    for (int i = 0; i < QPW; i++) {
        mx[i]  = mxd[i] / SQRT3;
        thr[i] = (mx[i] - 88.0f) * SQRT3;   // conservative dot-space prefilter
    }

    // ---- pass 2 (fused): sum of exp AND unnormalized weighted coords ----
    float sum[QPW], c0[QPW], c1[QPW], c2[QPW];
    #pragma unroll
    for (int i = 0; i < QPW; i++) { sum[i] = 0; c0[i] = 0; c1[i] = 0; c2[i] = 0; }
    {
        int m = lane;
        for (; m + 96 < kc; m += 128) {
            float4 ka = kl[m], kb = kl[m + 32], kd = kl[m + 64], ke = kl[m + 96];
            P2BODY(ka) P2BODY(kb) P2BODY(kd) P2BODY(ke)
        }
        for (; m < kc; m += 32) { float4 ka = kl[m]; P2BODY(ka) }
    }
    #pragma unroll
    for (int o = 16; o; o >>= 1)
        #pragma unroll
        for (int i = 0; i < QPW; i++) {
            sum[i] += __shfl_xor_sync(0xffffffffu, sum[i], o);
            c0[i]  += __shfl_xor_sync(0xffffffffu, c0[i], o);
            c1[i]  += __shfl_xor_sync(0xffffffffu, c1[i], o);
            c2[i]  += __shfl_xor_sync(0xffffffffu, c2[i], o);
        }

    // ---- MLP + logistic: lane i handles query i ----
    #pragma unroll
    for (int i = 0; i < QPW; i++) {
        if (lane == i) {
            float C0 = c0[i] / sum[i];
            float C1 = c1[i] / sum[i];
            float C2 = c2[i] / sum[i];
            float logit = 0.0f;
            #pragma unroll
            for (int j = 0; j < 32; j++) {
                float h = C0 * w1[j];
                h = fmaf(C1, w1[32 + j], h);
                h = fmaf(C2, w1[64 + j], h);
                h = h + b1[j];
                h = fmaxf(h, 0.0f);
                logit = fmaf(h, w2[j], logit);
            }
            logit = logit + b2[0];
            imp_out[qi[i]] = 0.5f + 0.5f * tanh_xla(0.5f * logit);
        }
    }
}

// ---- stable-ascending rank via pairwise counting; 2 voxels per warp ----
#define VPW 2
__global__ __launch_bounds__(256) void rank_kernel(
    const float* __restrict__ imp,
    const int*   __restrict__ vc,
    const float* __restrict__ voxels,
    float*       __restrict__ out)
{
    int warp = (blockIdx.x * blockDim.x + threadIdx.x) >> 5;
    int lane = threadIdx.x & 31;
    if (warp >= NQ / VPW) return;

    int base = VPW * warp;
    float my[VPW];
    #pragma unroll
    for (int i = 0; i < VPW; i++) my[i] = imp[base + i];

    int cnt[VPW];
    #pragma unroll
    for (int i = 0; i < VPW; i++) cnt[i] = 0;

    const float4* imp4 = (const float4*)imp;
    #pragma unroll 4
    for (int j4 = lane; j4 < NQ / 4; j4 += 32) {
        float4 v = imp4[j4];
        int j = 4 * j4;
        #pragma unroll
        for (int i = 0; i < VPW; i++) {
            int q = base + i;
            cnt[i] += (int)(v.x < my[i]) + (int)((v.x == my[i]) && (j + 0 < q));
            cnt[i] += (int)(v.y < my[i]) + (int)((v.y == my[i]) && (j + 1 < q));
            cnt[i] += (int)(v.z < my[i]) + (int)((v.z == my[i]) && (j + 2 < q));
            cnt[i] += (int)(v.w < my[i]) + (int)((v.w == my[i]) && (j + 3 < q));
        }
    }
    #pragma unroll
    for (int o = 16; o; o >>= 1)
        #pragma unroll
        for (int i = 0; i < VPW; i++)
            cnt[i] += __shfl_xor_sync(0xffffffffu, cnt[i], o);

    #pragma unroll
    for (int i = 0; i < VPW; i++) {
        if (cnt[i] >= KEEP) {
            int q = base + i;
            int row = cnt[i] - KEEP;
            if (lane < 20)
                out[OFF_VOX + row * 20 + lane] = voxels[q * 20 + lane];
            if (lane < 4)
                out[OFF_COORDS + row * 4 + lane] = (float)vc[q * 4 + lane];
            if (lane == 0)
                out[OFF_KIMP + row] = my[i];
        }
    }
}

extern "C" void kernel_launch(void* const* d_in, const int* in_sizes, int n_in,
                              void* d_out, int out_size) {
    const int*   vc     = (const int*)d_in[0];
    const float* keys   = (const float*)d_in[1];
    const float* voxels = (const float*)d_in[2];
    const float* w1     = (const float*)d_in[3];
    const float* b1     = (const float*)d_in[4];
    const float* w2     = (const float*)d_in[5];
    const float* b2     = (const float*)d_in[6];
    float* out = (float*)d_out;
    float* imp = out + OFF_IMP;

    count_kernel<<<64, 256>>>((const int4*)vc, (const float4*)keys);
    scatter_kernel<<<64, 256>>>((const int4*)vc, (const float4*)keys);
    // (NQ/QPW + 1 slack groups) warps, 8 warps per block
    attn_kernel<<<(NQ / QPW / 8) + 2, 256>>>((const int4*)vc, w1, b1, w2, b2, imp);
    rank_kernel<<<NQ / VPW / 8, 256>>>(imp, vc, voxels, out);
}

// round 11
// speedup vs baseline: 3.7950x; 1.3740x over previous
#include <cuda_runtime.h>
#include <cuda_bf16.h>
#include <cstdint>

#define NQ 8192
#define NK 8192
#define KEEP 4096

// Concatenated float32 output offsets
#define OFF_COORDS 0
#define OFF_VOX    16384
#define OFF_KIMP   98304
#define OFF_IMP    102400

#define SQRT3 1.7320508075688772f

typedef unsigned long long u64;

// ---- persistent device scratch (allocation-free) ----
__device__ __align__(16) float g_kz[2][NK];   // key z-coord, grouped by batch, stable order
__device__ __align__(16) float g_ky[2][NK];   // key y-coord
__device__ __align__(16) float g_kx[2][NK];   // key x-coord
__device__ int    g_kcnt[2];
__device__ int    g_qidx[2][NQ];              // query indices grouped by batch, stable
__device__ int    g_qcnt[2];
__device__ int    g_bc[64];                   // per-block batch-0 counts
__device__ __align__(16) u64 g_key64[NQ];     // (float_bits(imp)<<13)|idx : stable sort key

// ---- packed f32x2 helpers (IEEE per-lane, bit-identical to scalar) ----
__device__ __forceinline__ u64 mul2(u64 a, u64 b) {
    u64 d; asm("mul.rn.f32x2 %0, %1, %2;" : "=l"(d) : "l"(a), "l"(b)); return d;
}
__device__ __forceinline__ u64 fma2(u64 a, u64 b, u64 c) {
    u64 d; asm("fma.rn.f32x2 %0, %1, %2, %3;" : "=l"(d) : "l"(a), "l"(b), "l"(c)); return d;
}
__device__ __forceinline__ u64 pack2(float v) {
    u64 d; asm("mov.b64 %0, {%1, %1};" : "=l"(d) : "f"(v)); return d;
}
__device__ __forceinline__ float2 unpack2(u64 v) {
    float2 f; asm("mov.b64 {%0, %1}, %2;" : "=f"(f.x), "=f"(f.y) : "l"(v)); return f;
}

// XLA EmitFastTanh (Eigen ptanh<float>) — exact coefficients, clamp, small-x path.
__device__ __forceinline__ float tanh_xla(float x) {
    float ax = fabsf(x);
    float xc = fminf(fmaxf(x, -7.90531110763549805f), 7.90531110763549805f);
    float x2 = xc * xc;
    float p = fmaf(x2, -2.76076847742355e-16f, 2.00018790482477e-13f);
    p = fmaf(x2, p, -8.60467152213735e-11f);
    p = fmaf(x2, p, 5.12229709037114e-08f);
    p = fmaf(x2, p, 1.48572235717979e-05f);
    p = fmaf(x2, p, 6.37261928875436e-04f);
    p = fmaf(x2, p, 4.89352455891786e-03f);
    p = xc * p;
    float q = fmaf(x2, 1.19825839466702e-06f, 1.18534705686654e-04f);
    q = fmaf(x2, q, 2.26843463243900e-03f);
    q = fmaf(x2, q, 4.89352518554385e-03f);
    float r = p / q;
    return (ax < 0.0004f) ? x : r;
}

// ---- partition phase 1: per-block batch-0 counts (64 blocks x 256 threads) ----
__global__ __launch_bounds__(256) void count_kernel(
    const int4* __restrict__ vc, const float4* __restrict__ keys)
{
    __shared__ int ws[8];
    int b = blockIdx.x, t = threadIdx.x;
    int flag;
    if (b < 32) flag = (keys[b * 256 + t].x == 0.0f) ? 1 : 0;
    else        flag = (vc[(b - 32) * 256 + t].x == 0) ? 1 : 0;
    unsigned bal = __ballot_sync(0xffffffffu, flag);
    if ((t & 31) == 0) ws[t >> 5] = __popc(bal);
    __syncthreads();
    if (t == 0) {
        int s = 0;
        #pragma unroll
        for (int i = 0; i < 8; i++) s += ws[i];
        g_bc[b] = s;
    }
}

// ---- partition phase 2: stable scatter to SoA (64 blocks x 256 threads) ----
__global__ __launch_bounds__(256) void scatter_kernel(
    const int4* __restrict__ vc, const float4* __restrict__ keys)
{
    __shared__ int ws[8];
    __shared__ int s_pre0, s_tot0;
    int b = blockIdx.x, t = threadIdx.x;
    bool isKey = (b < 32);
    int c = isKey ? b : b - 32;
    int grp = isKey ? 0 : 32;

    if (t < 32) {
        int v = g_bc[grp + t];
        int x = v;
        #pragma unroll
        for (int o = 1; o < 32; o <<= 1) {
            int y = __shfl_up_sync(0xffffffffu, x, o);
            if (t >= o) x += y;
        }
        if (t == c)  s_pre0 = x - v;
        if (t == 31) s_tot0 = x;
    }
    __syncthreads();

    int i = c * 256 + t;
    int flag;
    float4 kv; int4 qv;
    if (isKey) { kv = keys[i]; flag = (kv.x == 0.0f) ? 1 : 0; }
    else       { qv = vc[i];   flag = (qv.x == 0) ? 1 : 0; }

    unsigned bal = __ballot_sync(0xffffffffu, flag);
    int lane = t & 31, w = t >> 5;
    int lpre = __popc(bal & ((1u << lane) - 1u));
    if (lane == 0) ws[w] = __popc(bal);
    __syncthreads();
    int wpre = 0;
    for (int j = 0; j < w; j++) wpre += ws[j];

    int pos0 = s_pre0 + wpre + lpre;
    int pos1 = i - pos0;
    if (isKey) {
        int bb = flag ? 0 : 1;
        int pp = flag ? pos0 : pos1;
        g_kz[bb][pp] = kv.y;
        g_ky[bb][pp] = kv.z;
        g_kx[bb][pp] = kv.w;
        if (t == 0 && c == 0) { g_kcnt[0] = s_tot0; g_kcnt[1] = NK - s_tot0; }
    } else {
        if (flag) g_qidx[0][pos0] = i; else g_qidx[1][pos1] = i;
        if (t == 0 && c == 0) { g_qcnt[0] = s_tot0; g_qcnt[1] = NQ - s_tot0; }
    }
}

// ---- attention: 2 same-batch queries per warp; SoA keys; packed f32x2 dots ----
#define QPW 2

__global__ __launch_bounds__(256) void attn_kernel(
    const int4*  __restrict__ vc,
    const float* __restrict__ w1,
    const float* __restrict__ b1,
    const float* __restrict__ w2,
    const float* __restrict__ b2,
    float*       __restrict__ imp_out)
{
    int warp = (blockIdx.x * blockDim.x + threadIdx.x) >> 5;
    int lane = threadIdx.x & 31;

    int qc0 = g_qcnt[0], qc1 = g_qcnt[1];
    int ngrp0 = (qc0 + QPW - 1) / QPW;
    int ngrp1 = (qc1 + QPW - 1) / QPW;
    int b, g, qc;
    if (warp < ngrp0)              { b = 0; g = warp;         qc = qc0; }
    else if (warp < ngrp0 + ngrp1) { b = 1; g = warp - ngrp0; qc = qc1; }
    else return;
    if (qc == 0) return;

    int qi[QPW];
    float qzs[QPW], qys[QPW], qxs[QPW];
    u64 qz2[QPW], qy2[QPW], qx2[QPW];
    #pragma unroll
    for (int i = 0; i < QPW; i++) {
        int idx = QPW * g + i;
        qi[i] = g_qidx[b][idx < qc ? idx : qc - 1];
        int4 q = vc[qi[i]];
        qzs[i] = (float)q.y; qys[i] = (float)q.z; qxs[i] = (float)q.w;
        qz2[i] = pack2(qzs[i]); qy2[i] = pack2(qys[i]); qx2[i] = pack2(qxs[i]);
    }

    const ulonglong2* z2 = (const ulonglong2*)g_kz[b];
    const ulonglong2* y2 = (const ulonglong2*)g_ky[b];
    const ulonglong2* x2 = (const ulonglong2*)g_kx[b];
    const float* kzs = g_kz[b];
    const float* kys = g_ky[b];
    const float* kxs = g_kx[b];
    int kc = g_kcnt[b];
    int nfull = kc & ~127;          // 128 keys per warp-iteration

    // ---- pass 1: max in dot-space (exact; order-free) ----
    float mxd[QPW];
    #pragma unroll
    for (int i = 0; i < QPW; i++) mxd[i] = -3.0e38f;

    for (int base = 0; base < nfull; base += 128) {
        int m2 = (base >> 2) + lane;          // ulonglong2 index: 4 keys
        ulonglong2 zz = z2[m2], yy = y2[m2], xx = x2[m2];
        #pragma unroll
        for (int i = 0; i < QPW; i++) {
            u64 d01 = fma2(qx2[i], xx.x, fma2(qy2[i], yy.x, mul2(qz2[i], zz.x)));
            u64 d23 = fma2(qx2[i], xx.y, fma2(qy2[i], yy.y, mul2(qz2[i], zz.y)));
            float2 a = unpack2(d01), c = unpack2(d23);
            mxd[i] = fmaxf(mxd[i],
                     fmaxf(fmaxf(a.x, a.y), fmaxf(c.x, c.y)));
        }
    }
    for (int m = nfull + lane; m < kc; m += 32) {
        float kz = kzs[m], ky = kys[m], kx = kxs[m];
        #pragma unroll
        for (int i = 0; i < QPW; i++) {
            float d = fmaf(qxs[i], kx, fmaf(qys[i], ky, qzs[i] * kz));
            mxd[i] = fmaxf(mxd[i], d);
        }
    }
    #pragma unroll
    for (int o = 16; o; o >>= 1)
        #pragma unroll
        for (int i = 0; i < QPW; i++)
            mxd[i] = fmaxf(mxd[i], __shfl_xor_sync(0xffffffffu, mxd[i], o));

    float mx[QPW], thr[QPW];
    #pragma unroll
    for (int i = 0; i < QPW; i++) {
        mx[i]  = mxd[i] / SQRT3;              // == max(dot/sqrt3), monotone
        thr[i] = (mx[i] - 88.0f) * SQRT3;     // conservative dot-space prefilter
    }

    // ---- pass 2 (fused): sum of exp AND unnormalized weighted coords ----
    float sum[QPW], c0[QPW], c1[QPW], c2[QPW];
    #pragma unroll
    for (int i = 0; i < QPW; i++) { sum[i] = 0; c0[i] = 0; c1[i] = 0; c2[i] = 0; }

    for (int base = 0; base < nfull; base += 128) {
        int m2 = (base >> 2) + lane;
        ulonglong2 zz = z2[m2], yy = y2[m2], xx = x2[m2];
        #pragma unroll
        for (int i = 0; i < QPW; i++) {
            u64 d01 = fma2(qx2[i], xx.x, fma2(qy2[i], yy.x, mul2(qz2[i], zz.x)));
            u64 d23 = fma2(qx2[i], xx.y, fma2(qy2[i], yy.y, mul2(qz2[i], zz.y)));
            float2 a = unpack2(d01), c = unpack2(d23);
            float md = fmaxf(fmaxf(a.x, a.y), fmaxf(c.x, c.y));
            if (md > thr[i]) {                 // rare path
                float ds[4] = {a.x, a.y, c.x, c.y};
                float2 kzp0 = unpack2(zz.x), kzp1 = unpack2(zz.y);
                float2 kyp0 = unpack2(yy.x), kyp1 = unpack2(yy.y);
                float2 kxp0 = unpack2(xx.x), kxp1 = unpack2(xx.y);
                float kzv[4] = {kzp0.x, kzp0.y, kzp1.x, kzp1.y};
                float kyv[4] = {kyp0.x, kyp0.y, kyp1.x, kyp1.y};
                float kxv[4] = {kxp0.x, kxp0.y, kxp1.x, kxp1.y};
                #pragma unroll
                for (int e = 0; e < 4; e++) {
                    float d = ds[e];
                    if (d > thr[i]) {
                        float s = d / SQRT3;
                        float t2 = s - mx[i];
                        if (t2 > -80.0f) {
                            float aa = expf(t2);
                            sum[i] += aa;
                            c0[i] = fmaf(aa, kzv[e], c0[i]);
                            c1[i] = fmaf(aa, kyv[e], c1[i]);
                            c2[i] = fmaf(aa, kxv[e], c2[i]);
                        }
                    }
                }
            }
        }
    }
    for (int m = nfull + lane; m < kc; m += 32) {
        float kz = kzs[m], ky = kys[m], kx = kxs[m];
        #pragma unroll
        for (int i = 0; i < QPW; i++) {
            float d = fmaf(qxs[i], kx, fmaf(qys[i], ky, qzs[i] * kz));
            if (d > thr[i]) {
                float s = d / SQRT3;
                float t2 = s - mx[i];
                if (t2 > -80.0f) {
                    float aa = expf(t2);
                    sum[i] += aa;
                    c0[i] = fmaf(aa, kz, c0[i]);
                    c1[i] = fmaf(aa, ky, c1[i]);
                    c2[i] = fmaf(aa, kx, c2[i]);
                }
            }
        }
    }
    #pragma unroll
    for (int o = 16; o; o >>= 1)
        #pragma unroll
        for (int i = 0; i < QPW; i++) {
            sum[i] += __shfl_xor_sync(0xffffffffu, sum[i], o);
            c0[i]  += __shfl_xor_sync(0xffffffffu, c0[i], o);
            c1[i]  += __shfl_xor_sync(0xffffffffu, c1[i], o);
            c2[i]  += __shfl_xor_sync(0xffffffffu, c2[i], o);
        }

    // ---- MLP + logistic; also emit the 64-bit stable-sort key ----
    #pragma unroll
    for (int i = 0; i < QPW; i++) {
        if (lane == i) {
            float C0 = c0[i] / sum[i];
            float C1 = c1[i] / sum[i];
            float C2 = c2[i] / sum[i];
            float logit = 0.0f;
            #pragma unroll
            for (int j = 0; j < 32; j++) {
                float h = C0 * w1[j];
                h = fmaf(C1, w1[32 + j], h);
                h = fmaf(C2, w1[64 + j], h);
                h = h + b1[j];
                h = fmaxf(h, 0.0f);
                logit = fmaf(h, w2[j], logit);
            }
            logit = logit + b2[0];
            float impv = 0.5f + 0.5f * tanh_xla(0.5f * logit);
            imp_out[qi[i]] = impv;
            // impv >= 0 => float bits monotone as unsigned; index breaks ties stably
            g_key64[qi[i]] = ((u64)__float_as_uint(impv) << 13) | (u64)qi[i];
        }
    }
}

// ---- stable-ascending rank = #{key_j < key_my} on unique u64 keys ----
#define VPW 2
__global__ __launch_bounds__(256) void rank_kernel(
    const float* __restrict__ imp,
    const int*   __restrict__ vc,
    const float* __restrict__ voxels,
    float*       __restrict__ out)
{
    int warp = (blockIdx.x * blockDim.x + threadIdx.x) >> 5;
    int lane = threadIdx.x & 31;
    if (warp >= NQ / VPW) return;

    int base = VPW * warp;
    u64 myk[VPW];
    #pragma unroll
    for (int i = 0; i < VPW; i++) myk[i] = g_key64[base + i];

    int cnt[VPW];
    #pragma unroll
    for (int i = 0; i < VPW; i++) cnt[i] = 0;

    const ulonglong2* k2 = (const ulonglong2*)g_key64;
    #pragma unroll 4
    for (int j2 = lane; j2 < NQ / 2; j2 += 32) {
        ulonglong2 kk = k2[j2];
        #pragma unroll
        for (int i = 0; i < VPW; i++) {
            cnt[i] += (int)(kk.x < myk[i]) + (int)(kk.y < myk[i]);
        }
    }
    #pragma unroll
    for (int o = 16; o; o >>= 1)
        #pragma unroll
        for (int i = 0; i < VPW; i++)
            cnt[i] += __shfl_xor_sync(0xffffffffu, cnt[i], o);

    #pragma unroll
    for (int i = 0; i < VPW; i++) {
        if (cnt[i] >= KEEP) {
            int q = base + i;
            int row = cnt[i] - KEEP;
            if (lane < 20)
                out[OFF_VOX + row * 20 + lane] = voxels[q * 20 + lane];
            if (lane < 4)
                out[OFF_COORDS + row * 4 + lane] = (float)vc[q * 4 + lane];
            if (lane == 0)
                out[OFF_KIMP + row] = imp[q];
        }
    }
}

extern "C" void kernel_launch(void* const* d_in, const int* in_sizes, int n_in,
                              void* d_out, int out_size) {
    const int*   vc     = (const int*)d_in[0];
    const float* keys   = (const float*)d_in[1];
    const float* voxels = (const float*)d_in[2];
    const float* w1     = (const float*)d_in[3];
    const float* b1     = (const float*)d_in[4];
    const float* w2     = (const float*)d_in[5];
    const float* b2     = (const float*)d_in[6];
    float* out = (float*)d_out;
    float* imp = out + OFF_IMP;

    count_kernel<<<64, 256>>>((const int4*)vc, (const float4*)keys);
    scatter_kernel<<<64, 256>>>((const int4*)vc, (const float4*)keys);
    attn_kernel<<<(NQ / QPW / 8) + 2, 256>>>((const int4*)vc, w1, b1, w2, b2, imp);
    rank_kernel<<<NQ / VPW / 8, 256>>>(imp, vc, voxels, out);
}